// round 2
// baseline (speedup 1.0000x reference)
#include <cuda_runtime.h>

// CounterfactualMultiheadAttention, algebraically reduced.
//
// attn_weights[b,h,q,k] = unmasked[b,k] ? 1/c_b : 0   (c_b = #unmasked keys)
// ctx[b,l,:]            = (mean over unmasked l' of value[b,l',:]) @ Wv.T + bv
// output[b,l,:]         = ctx_row[b] @ Wo.T + bo      (same for every l)
//
// Q, K, Wq, bq, Wk, bk are mathematically dead.
// key_padding_mask is bool in the reference -> materialized as int32 by harness.

#define B 4
#define L 1024
#define D 1024
#define H 16

// Scratch (no allocations allowed; device globals are the sanctioned path).
__device__ float g_vsum[B][D];     // column sums of value over unmasked rows
__device__ float g_vbar[B][D];     // vmean @ Wv.T + bv
__device__ float g_outrow[B][D];   // vbar  @ Wo.T + bo
__device__ float g_invc[B];        // 1 / c_b
__device__ float g_awrow[B][L];    // per-(b,k) counterfactual weight

// ---------------------------------------------------------------------------
// Kernel 1: per-batch unmasked count + counterfactual weight row.
// grid = B blocks, L threads. mask is int32 (0 = keep, nonzero = masked out).
__global__ void count_kernel(const int* __restrict__ mask) {
    int b = blockIdx.x;
    int t = threadIdx.x;
    __shared__ int s_cnt;
    if (t == 0) s_cnt = 0;
    __syncthreads();

    int m = mask[b * L + t];
    int local = m ? 0 : 1;
    #pragma unroll
    for (int o = 16; o; o >>= 1) local += __shfl_down_sync(0xFFFFFFFFu, local, o);
    if ((t & 31) == 0) atomicAdd(&s_cnt, local);
    __syncthreads();

    int c = s_cnt;
    float inv = 1.0f / (float)(c > 0 ? c : 1);
    if (t == 0) g_invc[b] = inv;
    g_awrow[b][t] = m ? 0.0f : inv;
}

// ---------------------------------------------------------------------------
// Kernel 2: masked column sums of value: g_vsum[b][j] = sum_{l unmasked} value[b,l,j]
// grid = (D/256, B), 256 threads. Coalesced 1KB rows per iteration.
__global__ void colsum_kernel(const float* __restrict__ value,
                              const int* __restrict__ mask) {
    int b = blockIdx.y;
    int j = blockIdx.x * 256 + threadIdx.x;

    __shared__ int s_mask[L];
    for (int i = threadIdx.x; i < L; i += 256) s_mask[i] = mask[b * L + i];
    __syncthreads();

    const float* base = value + (size_t)b * L * D + j;
    float acc = 0.0f;
    #pragma unroll 4
    for (int l = 0; l < L; l++) {
        float v = base[(size_t)l * D];           // always load (keeps MLP high)
        acc += s_mask[l] ? 0.0f : v;
    }
    g_vsum[b][j] = acc;
}

// ---------------------------------------------------------------------------
// Kernel 3: GEMV, warp-per-output-row, all 4 batches per warp.
// mode 0: g_vbar   = (g_vsum * invc) @ Wv.T + bv
// mode 1: g_outrow =  g_vbar        @ Wo.T + bo
// grid = D/8 blocks, 256 threads (8 warps).
__global__ void gemv_kernel(const float* __restrict__ W,
                            const float* __restrict__ bias, int mode) {
    __shared__ float s_in[B][D];   // 16 KB
    int tid = threadIdx.x;
    for (int i = tid; i < B * D; i += blockDim.x) {
        int b = i >> 10, j = i & (D - 1);
        s_in[b][j] = (mode == 0) ? g_vsum[b][j] * g_invc[b] : g_vbar[b][j];
    }
    __syncthreads();

    int warp = tid >> 5, lane = tid & 31;
    int j = blockIdx.x * 8 + warp;
    const float* wrow = W + (size_t)j * D;

    float a0 = 0.f, a1 = 0.f, a2 = 0.f, a3 = 0.f;
    for (int i = lane; i < D; i += 32) {
        float w = wrow[i];
        a0 += s_in[0][i] * w;
        a1 += s_in[1][i] * w;
        a2 += s_in[2][i] * w;
        a3 += s_in[3][i] * w;
    }
    #pragma unroll
    for (int o = 16; o; o >>= 1) {
        a0 += __shfl_down_sync(0xFFFFFFFFu, a0, o);
        a1 += __shfl_down_sync(0xFFFFFFFFu, a1, o);
        a2 += __shfl_down_sync(0xFFFFFFFFu, a2, o);
        a3 += __shfl_down_sync(0xFFFFFFFFu, a3, o);
    }
    if (lane == 0) {
        float bb = bias[j];
        if (mode == 0) {
            g_vbar[0][j] = a0 + bb; g_vbar[1][j] = a1 + bb;
            g_vbar[2][j] = a2 + bb; g_vbar[3][j] = a3 + bb;
        } else {
            g_outrow[0][j] = a0 + bb; g_outrow[1][j] = a1 + bb;
            g_outrow[2][j] = a2 + bb; g_outrow[3][j] = a3 + bb;
        }
    }
}

// ---------------------------------------------------------------------------
// Kernel 4: broadcast output rows: out[b,l,:] = g_outrow[b]. float4 writes.
// total float4 elems = B*L*D/4 = 1,048,576.
__global__ void bcast_out_kernel(float4* __restrict__ out) {
    int idx = blockIdx.x * blockDim.x + threadIdx.x;
    int j4 = idx & (D / 4 - 1);          // 0..255
    int b  = idx >> 18;                  // idx / (L * D/4)
    out[idx] = reinterpret_cast<const float4*>(g_outrow[b])[j4];
}

// ---------------------------------------------------------------------------
// Kernel 5: fill attn_weights[b,h,q,k] = g_awrow[b][k]. float4 writes.
// total float4 elems = B*H*L*L/4 = 16,777,216.
__global__ void attn_fill_kernel(float4* __restrict__ aw) {
    unsigned idx = blockIdx.x * blockDim.x + threadIdx.x;
    unsigned k4 = idx & (L / 4 - 1);     // 0..255
    unsigned b  = idx >> 22;             // idx / (H * L * L/4) = idx / 4,194,304
    aw[idx] = reinterpret_cast<const float4*>(g_awrow[b])[k4];
}

// ---------------------------------------------------------------------------
extern "C" void kernel_launch(void* const* d_in, const int* in_sizes, int n_in,
                              void* d_out, int out_size) {
    // Input order: query, key, value, key_padding_mask, Wq, bq, Wk, bk, Wv, bv, Wo, bo
    const float* value = (const float*)d_in[2];
    const int*   mask  = (const int*)d_in[3];
    const float* Wv    = (const float*)d_in[8];
    const float* bv    = (const float*)d_in[9];
    const float* Wo    = (const float*)d_in[10];
    const float* bo    = (const float*)d_in[11];
    float* out = (float*)d_out;

    const long long OUT_ELEMS  = (long long)B * L * D;          //  4,194,304
    const long long ATTN_ELEMS = (long long)B * H * L * L;      // 67,108,864

    count_kernel<<<B, L>>>(mask);
    colsum_kernel<<<dim3(D / 256, B), 256>>>(value, mask);
    gemv_kernel<<<D / 8, 256>>>(Wv, bv, 0);
    gemv_kernel<<<D / 8, 256>>>(Wo, bo, 1);

    if ((long long)out_size >= OUT_ELEMS + ATTN_ELEMS) {
        // Tuple concatenated: [output, attn_weights]
        bcast_out_kernel<<<(int)(OUT_ELEMS / 4 / 256), 256>>>((float4*)out);
        attn_fill_kernel<<<(int)(ATTN_ELEMS / 4 / 256), 256>>>(
            (float4*)(out + OUT_ELEMS));
    } else if ((long long)out_size >= ATTN_ELEMS) {
        // attn_weights only
        attn_fill_kernel<<<(int)(ATTN_ELEMS / 4 / 256), 256>>>((float4*)out);
    } else {
        // output only
        bcast_out_kernel<<<(int)(OUT_ELEMS / 4 / 256), 256>>>((float4*)out);
    }
}

// round 3
// speedup vs baseline: 3.0761x; 3.0761x over previous
#include <cuda_runtime.h>

// CounterfactualMultiheadAttention, algebraically reduced.
//
// attn_weights[b,h,q,k] = unmasked[b,k] ? 1/c_b : 0   (c_b = #unmasked keys)
// ctx[b,l,:]            = (mean over unmasked l' of value[b,l',:]) @ Wv.T + bv
// output[b,l,:]         = ctx_row[b] @ Wo.T + bo      (same for every l)
//
// Q, K, Wq, bq, Wk, bk are mathematically dead.
// key_padding_mask is bool in the reference -> materialized as int32 by harness.

#define B 4
#define L 1024
#define D 1024
#define H 16
#define ROWS_PER_BLK 32   // colsum row-slice size

// Scratch (no allocations allowed; device globals are the sanctioned path).
__device__ float g_vsum[B][D];     // column sums of value over unmasked rows
__device__ float g_vbar[B][D];     // vmean @ Wv.T + bv
__device__ float g_outrow[B][D];   // vbar  @ Wo.T + bo
__device__ float g_invc[B];        // 1 / c_b
__device__ float g_awrow[B][L];    // per-(b,k) counterfactual weight

// ---------------------------------------------------------------------------
// Kernel 1: per-batch unmasked count + counterfactual weight row.
// Also zeroes g_vsum (4 blocks x 1024 threads == B*D elements) so the
// atomic-accumulating colsum kernel is graph-replay safe.
// grid = B blocks, L threads. mask is int32 (0 = keep, nonzero = masked out).
__global__ void count_kernel(const int* __restrict__ mask) {
    int b = blockIdx.x;
    int t = threadIdx.x;

    g_vsum[b][t] = 0.0f;           // replay-safe re-init

    __shared__ int s_cnt;
    if (t == 0) s_cnt = 0;
    __syncthreads();

    int m = mask[b * L + t];
    int local = m ? 0 : 1;
    #pragma unroll
    for (int o = 16; o; o >>= 1) local += __shfl_down_sync(0xFFFFFFFFu, local, o);
    if ((t & 31) == 0) atomicAdd(&s_cnt, local);
    __syncthreads();

    int c = s_cnt;
    float inv = 1.0f / (float)(c > 0 ? c : 1);
    if (t == 0) g_invc[b] = inv;
    g_awrow[b][t] = m ? 0.0f : inv;
}

// ---------------------------------------------------------------------------
// Kernel 2: masked column partial sums of value, parallel over row slices.
// grid = (D/256, B, L/ROWS_PER_BLK) = (4, 4, 32) = 512 blocks, 256 threads.
// Each block sums ROWS_PER_BLK rows of its 256-column stripe, then one
// atomicAdd per thread into g_vsum (spread addresses -> REDG-cheap).
__global__ void colsum_kernel(const float* __restrict__ value,
                              const int* __restrict__ mask) {
    int b  = blockIdx.y;
    int j  = blockIdx.x * 256 + threadIdx.x;
    int l0 = blockIdx.z * ROWS_PER_BLK;

    __shared__ int s_mask[ROWS_PER_BLK];
    if (threadIdx.x < ROWS_PER_BLK)
        s_mask[threadIdx.x] = mask[b * L + l0 + threadIdx.x];
    __syncthreads();

    const float* base = value + (size_t)b * L * D + (size_t)l0 * D + j;
    float acc = 0.0f;
    #pragma unroll 8
    for (int l = 0; l < ROWS_PER_BLK; l++) {
        float v = base[(size_t)l * D];           // always load (keeps MLP high)
        acc += s_mask[l] ? 0.0f : v;
    }
    atomicAdd(&g_vsum[b][j], acc);
}

// ---------------------------------------------------------------------------
// Kernel 3: GEMV, warp-per-output-row, all 4 batches per warp, float4 loads.
// mode 0: g_vbar   = (g_vsum * invc) @ Wv.T + bv
// mode 1: g_outrow =  g_vbar        @ Wo.T + bo
// grid = D/8 blocks, 256 threads (8 warps).
__global__ void gemv_kernel(const float* __restrict__ W,
                            const float* __restrict__ bias, int mode) {
    __shared__ float s_in[B][D];   // 16 KB
    int tid = threadIdx.x;
    for (int i = tid; i < B * D; i += blockDim.x) {
        int b = i >> 10, j = i & (D - 1);
        s_in[b][j] = (mode == 0) ? g_vsum[b][j] * g_invc[b] : g_vbar[b][j];
    }
    __syncthreads();

    int warp = tid >> 5, lane = tid & 31;
    int j = blockIdx.x * 8 + warp;
    const float4* wrow = reinterpret_cast<const float4*>(W + (size_t)j * D);
    const float4* x0 = reinterpret_cast<const float4*>(s_in[0]);
    const float4* x1 = reinterpret_cast<const float4*>(s_in[1]);
    const float4* x2 = reinterpret_cast<const float4*>(s_in[2]);
    const float4* x3 = reinterpret_cast<const float4*>(s_in[3]);

    float a0 = 0.f, a1 = 0.f, a2 = 0.f, a3 = 0.f;
    #pragma unroll
    for (int i = lane; i < D / 4; i += 32) {
        float4 w = wrow[i];
        float4 v;
        v = x0[i]; a0 += w.x*v.x + w.y*v.y + w.z*v.z + w.w*v.w;
        v = x1[i]; a1 += w.x*v.x + w.y*v.y + w.z*v.z + w.w*v.w;
        v = x2[i]; a2 += w.x*v.x + w.y*v.y + w.z*v.z + w.w*v.w;
        v = x3[i]; a3 += w.x*v.x + w.y*v.y + w.z*v.z + w.w*v.w;
    }
    #pragma unroll
    for (int o = 16; o; o >>= 1) {
        a0 += __shfl_down_sync(0xFFFFFFFFu, a0, o);
        a1 += __shfl_down_sync(0xFFFFFFFFu, a1, o);
        a2 += __shfl_down_sync(0xFFFFFFFFu, a2, o);
        a3 += __shfl_down_sync(0xFFFFFFFFu, a3, o);
    }
    if (lane == 0) {
        float bb = bias[j];
        if (mode == 0) {
            g_vbar[0][j] = a0 + bb; g_vbar[1][j] = a1 + bb;
            g_vbar[2][j] = a2 + bb; g_vbar[3][j] = a3 + bb;
        } else {
            g_outrow[0][j] = a0 + bb; g_outrow[1][j] = a1 + bb;
            g_outrow[2][j] = a2 + bb; g_outrow[3][j] = a3 + bb;
        }
    }
}

// ---------------------------------------------------------------------------
// Kernel 4: broadcast output rows: out[b,l,:] = g_outrow[b]. float4 writes.
// total float4 elems = B*L*D/4 = 1,048,576.
__global__ void bcast_out_kernel(float4* __restrict__ out) {
    int idx = blockIdx.x * blockDim.x + threadIdx.x;
    int j4 = idx & (D / 4 - 1);          // 0..255
    int b  = idx >> 18;                  // idx / (L * D/4)
    out[idx] = reinterpret_cast<const float4*>(g_outrow[b])[j4];
}

// ---------------------------------------------------------------------------
// Kernel 5: fill attn_weights[b,h,q,k] = g_awrow[b][k]. float4 writes.
// total float4 elems = B*H*L*L/4 = 16,777,216.
__global__ void attn_fill_kernel(float4* __restrict__ aw) {
    unsigned idx = blockIdx.x * blockDim.x + threadIdx.x;
    unsigned k4 = idx & (L / 4 - 1);     // 0..255
    unsigned b  = idx >> 22;             // idx / (H * L * L/4) = idx / 4,194,304
    aw[idx] = reinterpret_cast<const float4*>(g_awrow[b])[k4];
}

// ---------------------------------------------------------------------------
extern "C" void kernel_launch(void* const* d_in, const int* in_sizes, int n_in,
                              void* d_out, int out_size) {
    // Input order: query, key, value, key_padding_mask, Wq, bq, Wk, bk, Wv, bv, Wo, bo
    const float* value = (const float*)d_in[2];
    const int*   mask  = (const int*)d_in[3];
    const float* Wv    = (const float*)d_in[8];
    const float* bv    = (const float*)d_in[9];
    const float* Wo    = (const float*)d_in[10];
    const float* bo    = (const float*)d_in[11];
    float* out = (float*)d_out;

    const long long OUT_ELEMS  = (long long)B * L * D;          //  4,194,304
    const long long ATTN_ELEMS = (long long)B * H * L * L;      // 67,108,864

    count_kernel<<<B, L>>>(mask);                       // also zeroes g_vsum
    colsum_kernel<<<dim3(D / 256, B, L / ROWS_PER_BLK), 256>>>(value, mask);
    gemv_kernel<<<D / 8, 256>>>(Wv, bv, 0);
    gemv_kernel<<<D / 8, 256>>>(Wo, bo, 1);

    if ((long long)out_size >= OUT_ELEMS + ATTN_ELEMS) {
        // Tuple concatenated: [output, attn_weights]
        bcast_out_kernel<<<(int)(OUT_ELEMS / 4 / 256), 256>>>((float4*)out);
        attn_fill_kernel<<<(int)(ATTN_ELEMS / 4 / 256), 256>>>(
            (float4*)(out + OUT_ELEMS));
    } else if ((long long)out_size >= ATTN_ELEMS) {
        // attn_weights only
        attn_fill_kernel<<<(int)(ATTN_ELEMS / 4 / 256), 256>>>((float4*)out);
    } else {
        // output only
        bcast_out_kernel<<<(int)(OUT_ELEMS / 4 / 256), 256>>>((float4*)out);
    }
}

// round 4
// speedup vs baseline: 3.2780x; 1.0656x over previous
#include <cuda_runtime.h>

// CounterfactualMultiheadAttention, algebraically reduced.
//
// attn_weights[b,h,q,k] = unmasked[b,k] ? 1/c_b : 0   (c_b = #unmasked keys)
// ctx[b,l,:]            = (mean over unmasked l' of value[b,l',:]) @ Wv.T + bv
// output[b,l,:]         = ctx_row[b] @ Wo.T + bo      (same for every l)
//
// Q, K, Wq, bq, Wk, bk are mathematically dead.
// key_padding_mask is bool in the reference -> materialized as int32 by harness.
//
// Two-stream graph: the 268MB attn_weights fill (depends only on the mask
// count) runs on a forked stream, hiding the colsum->gemv->gemv->bcast chain.

#define B 4
#define L 1024
#define D 1024
#define H 16
#define ROWS_PER_BLK 32   // colsum row-slice size
#define SPLITS 4          // gemv K-splits
#define KS (D / SPLITS)   // 256

// Scratch (no allocations allowed; device globals are the sanctioned path).
__device__ float g_vsum[B][D];     // column sums of value over unmasked rows
__device__ float g_vbar[B][D];     // vmean @ Wv.T + bv
__device__ float g_outrow[B][D];   // vbar  @ Wo.T + bo
__device__ float g_invc[B];        // 1 / c_b
__device__ float g_awrow[B][L];    // per-(b,k) counterfactual weight

// ---------------------------------------------------------------------------
// Kernel 1: per-batch unmasked count + counterfactual weight row.
// Also zeroes the atomic accumulators (B blocks x D threads covers [B][D])
// so the graph is replay-safe.
__global__ void count_kernel(const int* __restrict__ mask) {
    int b = blockIdx.x;
    int t = threadIdx.x;

    g_vsum[b][t]   = 0.0f;         // replay-safe re-init
    g_vbar[b][t]   = 0.0f;
    g_outrow[b][t] = 0.0f;

    __shared__ int s_cnt;
    if (t == 0) s_cnt = 0;
    __syncthreads();

    int m = mask[b * L + t];
    int local = m ? 0 : 1;
    #pragma unroll
    for (int o = 16; o; o >>= 1) local += __shfl_down_sync(0xFFFFFFFFu, local, o);
    if ((t & 31) == 0) atomicAdd(&s_cnt, local);
    __syncthreads();

    int c = s_cnt;
    float inv = 1.0f / (float)(c > 0 ? c : 1);
    if (t == 0) g_invc[b] = inv;
    g_awrow[b][t] = m ? 0.0f : inv;
}

// ---------------------------------------------------------------------------
// Kernel 2: masked column partial sums of value, parallel over row slices.
// grid = (D/256, B, L/ROWS_PER_BLK) = 512 blocks, 256 threads.
__global__ void colsum_kernel(const float* __restrict__ value,
                              const int* __restrict__ mask) {
    int b  = blockIdx.y;
    int j  = blockIdx.x * 256 + threadIdx.x;
    int l0 = blockIdx.z * ROWS_PER_BLK;

    __shared__ int s_mask[ROWS_PER_BLK];
    if (threadIdx.x < ROWS_PER_BLK)
        s_mask[threadIdx.x] = mask[b * L + l0 + threadIdx.x];
    __syncthreads();

    const float* base = value + (size_t)b * L * D + (size_t)l0 * D + j;
    float acc = 0.0f;
    #pragma unroll 8
    for (int l = 0; l < ROWS_PER_BLK; l++) {
        float v = base[(size_t)l * D];
        acc += s_mask[l] ? 0.0f : v;
    }
    atomicAdd(&g_vsum[b][j], acc);
}

// ---------------------------------------------------------------------------
// Kernel 3: split-K GEMV, warp-per-output-row, all 4 batches per warp.
// grid = (D/8, SPLITS), 256 threads. Each block handles a 256-wide K slice
// and atomicAdds its partial into the destination (zeroed by count_kernel).
// mode 0: g_vbar   += slice of (g_vsum * invc) @ Wv.T   (+ bv on split 0)
// mode 1: g_outrow += slice of  g_vbar         @ Wo.T   (+ bo on split 0)
__global__ void gemv_kernel(const float* __restrict__ W,
                            const float* __restrict__ bias, int mode) {
    int s  = blockIdx.y;
    int k0 = s * KS;

    __shared__ float s_in[B][KS];   // 4 KB
    int tid = threadIdx.x;
    for (int i = tid; i < B * KS; i += 256) {
        int b = i >> 8, j = i & (KS - 1);
        s_in[b][j] = (mode == 0) ? g_vsum[b][k0 + j] * g_invc[b]
                                 : g_vbar[b][k0 + j];
    }
    __syncthreads();

    int warp = tid >> 5, lane = tid & 31;
    int j = blockIdx.x * 8 + warp;
    const float4* wrow = reinterpret_cast<const float4*>(W + (size_t)j * D + k0);
    const float4* x0 = reinterpret_cast<const float4*>(s_in[0]);
    const float4* x1 = reinterpret_cast<const float4*>(s_in[1]);
    const float4* x2 = reinterpret_cast<const float4*>(s_in[2]);
    const float4* x3 = reinterpret_cast<const float4*>(s_in[3]);

    float a0 = 0.f, a1 = 0.f, a2 = 0.f, a3 = 0.f;
    #pragma unroll
    for (int i = lane; i < KS / 4; i += 32) {
        float4 w = wrow[i];
        float4 v;
        v = x0[i]; a0 += w.x*v.x + w.y*v.y + w.z*v.z + w.w*v.w;
        v = x1[i]; a1 += w.x*v.x + w.y*v.y + w.z*v.z + w.w*v.w;
        v = x2[i]; a2 += w.x*v.x + w.y*v.y + w.z*v.z + w.w*v.w;
        v = x3[i]; a3 += w.x*v.x + w.y*v.y + w.z*v.z + w.w*v.w;
    }
    #pragma unroll
    for (int o = 16; o; o >>= 1) {
        a0 += __shfl_down_sync(0xFFFFFFFFu, a0, o);
        a1 += __shfl_down_sync(0xFFFFFFFFu, a1, o);
        a2 += __shfl_down_sync(0xFFFFFFFFu, a2, o);
        a3 += __shfl_down_sync(0xFFFFFFFFu, a3, o);
    }
    if (lane == 0) {
        float bb = (s == 0) ? bias[j] : 0.0f;
        float* dst0 = (mode == 0) ? &g_vbar[0][j] : &g_outrow[0][j];
        float* dst1 = (mode == 0) ? &g_vbar[1][j] : &g_outrow[1][j];
        float* dst2 = (mode == 0) ? &g_vbar[2][j] : &g_outrow[2][j];
        float* dst3 = (mode == 0) ? &g_vbar[3][j] : &g_outrow[3][j];
        atomicAdd(dst0, a0 + bb);
        atomicAdd(dst1, a1 + bb);
        atomicAdd(dst2, a2 + bb);
        atomicAdd(dst3, a3 + bb);
    }
}

// ---------------------------------------------------------------------------
// Kernel 4: broadcast output rows: out[b,l,:] = g_outrow[b]. float4 writes.
__global__ void bcast_out_kernel(float4* __restrict__ out) {
    int idx = blockIdx.x * blockDim.x + threadIdx.x;
    int j4 = idx & (D / 4 - 1);          // 0..255
    int b  = idx >> 18;                  // idx / (L * D/4)
    out[idx] = reinterpret_cast<const float4*>(g_outrow[b])[j4];
}

// ---------------------------------------------------------------------------
// Kernel 5: fill attn_weights[b,h,q,k] = g_awrow[b][k]. float4 writes.
__global__ void attn_fill_kernel(float4* __restrict__ aw) {
    unsigned idx = blockIdx.x * blockDim.x + threadIdx.x;
    unsigned k4 = idx & (L / 4 - 1);     // 0..255
    unsigned b  = idx >> 22;             // idx / (H * L * L/4)
    aw[idx] = reinterpret_cast<const float4*>(g_awrow[b])[k4];
}

// ---------------------------------------------------------------------------
extern "C" void kernel_launch(void* const* d_in, const int* in_sizes, int n_in,
                              void* d_out, int out_size) {
    // Input order: query, key, value, key_padding_mask, Wq, bq, Wk, bk, Wv, bv, Wo, bo
    const float* value = (const float*)d_in[2];
    const int*   mask  = (const int*)d_in[3];
    const float* Wv    = (const float*)d_in[8];
    const float* bv    = (const float*)d_in[9];
    const float* Wo    = (const float*)d_in[10];
    const float* bo    = (const float*)d_in[11];
    float* out = (float*)d_out;

    const long long OUT_ELEMS  = (long long)B * L * D;          //  4,194,304
    const long long ATTN_ELEMS = (long long)B * H * L * L;      // 67,108,864

    cudaStream_t s0 = 0;                 // the capture/launch stream
    cudaStream_t s2;
    cudaStreamCreateWithFlags(&s2, cudaStreamNonBlocking);
    cudaEvent_t eFork, eJoin;
    cudaEventCreateWithFlags(&eFork, cudaEventDisableTiming);
    cudaEventCreateWithFlags(&eJoin, cudaEventDisableTiming);

    // Stage 0: counts + weight row + accumulator zeroing (both branches need it)
    count_kernel<<<B, L, 0, s0>>>(mask);

    // Fork: big attn_weights fill depends only on count_kernel.
    cudaEventRecord(eFork, s0);
    cudaStreamWaitEvent(s2, eFork, 0);

    if ((long long)out_size >= OUT_ELEMS + ATTN_ELEMS) {
        attn_fill_kernel<<<(int)(ATTN_ELEMS / 4 / 256), 256, 0, s2>>>(
            (float4*)(out + OUT_ELEMS));
    } else if ((long long)out_size >= ATTN_ELEMS) {
        attn_fill_kernel<<<(int)(ATTN_ELEMS / 4 / 256), 256, 0, s2>>>(
            (float4*)out);
    }

    // Main-stream chain: colsum -> gemvV -> gemvO -> bcast
    colsum_kernel<<<dim3(D / 256, B, L / ROWS_PER_BLK), 256, 0, s0>>>(value, mask);
    gemv_kernel<<<dim3(D / 8, SPLITS), 256, 0, s0>>>(Wv, bv, 0);
    gemv_kernel<<<dim3(D / 8, SPLITS), 256, 0, s0>>>(Wo, bo, 1);

    if ((long long)out_size >= OUT_ELEMS + ATTN_ELEMS ||
        (long long)out_size < ATTN_ELEMS) {
        bcast_out_kernel<<<(int)(OUT_ELEMS / 4 / 256), 256, 0, s0>>>((float4*)out);
    }

    // Join side stream back into the main stream.
    cudaEventRecord(eJoin, s2);
    cudaStreamWaitEvent(s0, eJoin, 0);

    cudaEventDestroy(eFork);
    cudaEventDestroy(eJoin);
    cudaStreamDestroy(s2);
}

// round 5
// speedup vs baseline: 3.2865x; 1.0026x over previous
#include <cuda_runtime.h>

// CounterfactualMultiheadAttention, algebraically reduced.
//
// attn_weights[b,h,q,k] = unmasked[b,k] ? 1/c_b : 0   (c_b = #unmasked keys)
// ctx[b,l,:]            = (mean over unmasked l' of value[b,l',:]) @ Wv.T + bv
// output[b,l,:]         = ctx_row[b] @ Wo.T + bo      (same for every l)
//
// Q, K, Wq, bq, Wk, bk are mathematically dead.
// key_padding_mask is bool in the reference -> int32 in the harness.
//
// Two-stream graph: the 268MB attn_weights fill (depends only on the mask
// count) overlaps the colsum->gemv->gemv->bcast chain. Fills are persistent
// single-wave kernels with loop-invariant values and evict-streaming stores.

#define B 4
#define L 1024
#define D 1024
#define H 16
#define ROWS_PER_BLK 32   // colsum row-slice size
#define SPLITS 4          // gemv K-splits
#define KS (D / SPLITS)   // 256

// Scratch (no allocations allowed; device globals are the sanctioned path).
__device__ float g_vsum[B][D];     // column sums of value over unmasked rows
__device__ float g_vbar[B][D];     // vmean @ Wv.T + bv
__device__ float g_outrow[B][D];   // vbar  @ Wo.T + bo
__device__ float g_invc[B];        // 1 / c_b
__device__ float g_awrow[B][L];    // per-(b,k) counterfactual weight

// ---------------------------------------------------------------------------
// Kernel 1: per-batch unmasked count + counterfactual weight row.
// Also zeroes the atomic accumulators (B blocks x D threads covers [B][D]).
__global__ void count_kernel(const int* __restrict__ mask) {
    int b = blockIdx.x;
    int t = threadIdx.x;

    g_vsum[b][t]   = 0.0f;         // replay-safe re-init
    g_vbar[b][t]   = 0.0f;
    g_outrow[b][t] = 0.0f;

    __shared__ int s_cnt;
    if (t == 0) s_cnt = 0;
    __syncthreads();

    int m = mask[b * L + t];
    int local = m ? 0 : 1;
    #pragma unroll
    for (int o = 16; o; o >>= 1) local += __shfl_down_sync(0xFFFFFFFFu, local, o);
    if ((t & 31) == 0) atomicAdd(&s_cnt, local);
    __syncthreads();

    int c = s_cnt;
    float inv = 1.0f / (float)(c > 0 ? c : 1);
    if (t == 0) g_invc[b] = inv;
    g_awrow[b][t] = m ? 0.0f : inv;
}

// ---------------------------------------------------------------------------
// Kernel 2: masked column partial sums of value, parallel over row slices.
// grid = (D/256, B, L/ROWS_PER_BLK) = 512 blocks, 256 threads.
__global__ void colsum_kernel(const float* __restrict__ value,
                              const int* __restrict__ mask) {
    int b  = blockIdx.y;
    int j  = blockIdx.x * 256 + threadIdx.x;
    int l0 = blockIdx.z * ROWS_PER_BLK;

    __shared__ int s_mask[ROWS_PER_BLK];
    if (threadIdx.x < ROWS_PER_BLK)
        s_mask[threadIdx.x] = mask[b * L + l0 + threadIdx.x];
    __syncthreads();

    const float* base = value + (size_t)b * L * D + (size_t)l0 * D + j;
    float acc = 0.0f;
    #pragma unroll 8
    for (int l = 0; l < ROWS_PER_BLK; l++) {
        float v = base[(size_t)l * D];
        acc += s_mask[l] ? 0.0f : v;
    }
    atomicAdd(&g_vsum[b][j], acc);
}

// ---------------------------------------------------------------------------
// Kernel 3: split-K GEMV, warp-per-output-row, all 4 batches per warp.
// grid = (D/8, SPLITS), 256 threads. Partial sums atomicAdd into destination.
__global__ void gemv_kernel(const float* __restrict__ W,
                            const float* __restrict__ bias, int mode) {
    int s  = blockIdx.y;
    int k0 = s * KS;

    __shared__ float s_in[B][KS];   // 4 KB
    int tid = threadIdx.x;
    for (int i = tid; i < B * KS; i += 256) {
        int b = i >> 8, j = i & (KS - 1);
        s_in[b][j] = (mode == 0) ? g_vsum[b][k0 + j] * g_invc[b]
                                 : g_vbar[b][k0 + j];
    }
    __syncthreads();

    int warp = tid >> 5, lane = tid & 31;
    int j = blockIdx.x * 8 + warp;
    const float4* wrow = reinterpret_cast<const float4*>(W + (size_t)j * D + k0);
    const float4* x0 = reinterpret_cast<const float4*>(s_in[0]);
    const float4* x1 = reinterpret_cast<const float4*>(s_in[1]);
    const float4* x2 = reinterpret_cast<const float4*>(s_in[2]);
    const float4* x3 = reinterpret_cast<const float4*>(s_in[3]);

    float a0 = 0.f, a1 = 0.f, a2 = 0.f, a3 = 0.f;
    #pragma unroll
    for (int i = lane; i < KS / 4; i += 32) {
        float4 w = wrow[i];
        float4 v;
        v = x0[i]; a0 += w.x*v.x + w.y*v.y + w.z*v.z + w.w*v.w;
        v = x1[i]; a1 += w.x*v.x + w.y*v.y + w.z*v.z + w.w*v.w;
        v = x2[i]; a2 += w.x*v.x + w.y*v.y + w.z*v.z + w.w*v.w;
        v = x3[i]; a3 += w.x*v.x + w.y*v.y + w.z*v.z + w.w*v.w;
    }
    #pragma unroll
    for (int o = 16; o; o >>= 1) {
        a0 += __shfl_down_sync(0xFFFFFFFFu, a0, o);
        a1 += __shfl_down_sync(0xFFFFFFFFu, a1, o);
        a2 += __shfl_down_sync(0xFFFFFFFFu, a2, o);
        a3 += __shfl_down_sync(0xFFFFFFFFu, a3, o);
    }
    if (lane == 0) {
        float bb = (s == 0) ? bias[j] : 0.0f;
        float* dst0 = (mode == 0) ? &g_vbar[0][j] : &g_outrow[0][j];
        float* dst1 = (mode == 0) ? &g_vbar[1][j] : &g_outrow[1][j];
        float* dst2 = (mode == 0) ? &g_vbar[2][j] : &g_outrow[2][j];
        float* dst3 = (mode == 0) ? &g_vbar[3][j] : &g_outrow[3][j];
        atomicAdd(dst0, a0 + bb);
        atomicAdd(dst1, a1 + bb);
        atomicAdd(dst2, a2 + bb);
        atomicAdd(dst3, a3 + bb);
    }
}

// ---------------------------------------------------------------------------
// Kernel 4: broadcast output rows, persistent. grid = (64, B), 256 threads.
// Per batch: 262144 float4; stride 16384 (mult of 256) => j4 loop-invariant.
__global__ void bcast_out_kernel(float4* __restrict__ out) {
    int b = blockIdx.y;
    int g = blockIdx.x * 256 + threadIdx.x;      // 0..16383
    int j4 = g & (D / 4 - 1);
    float4 v = reinterpret_cast<const float4*>(g_outrow[b])[j4];
    float4* dst = out + (size_t)b * (L * D / 4) + g;
    #pragma unroll
    for (int it = 0; it < 16; it++)
        __stcs(dst + it * 16384, v);
}

// ---------------------------------------------------------------------------
// Kernel 5: fill attn_weights[b,h,q,k] = g_awrow[b][k], persistent.
// grid = (256, B), 256 threads. Per batch: 4,194,304 float4; stride 65536
// (mult of 256) => k4 loop-invariant => value in a register; the loop is 64
// independent evict-streaming STG.128s.
__global__ void attn_fill_kernel(float4* __restrict__ aw) {
    int b = blockIdx.y;
    int g = blockIdx.x * 256 + threadIdx.x;      // 0..65535
    int k4 = g & (L / 4 - 1);
    float4 v = reinterpret_cast<const float4*>(g_awrow[b])[k4];
    float4* dst = aw + (size_t)b * (H * L * L / 4) + g;
    #pragma unroll
    for (int it = 0; it < 64; it++)
        __stcs(dst + it * 65536, v);
}

// ---------------------------------------------------------------------------
extern "C" void kernel_launch(void* const* d_in, const int* in_sizes, int n_in,
                              void* d_out, int out_size) {
    // Input order: query, key, value, key_padding_mask, Wq, bq, Wk, bk, Wv, bv, Wo, bo
    const float* value = (const float*)d_in[2];
    const int*   mask  = (const int*)d_in[3];
    const float* Wv    = (const float*)d_in[8];
    const float* bv    = (const float*)d_in[9];
    const float* Wo    = (const float*)d_in[10];
    const float* bo    = (const float*)d_in[11];
    float* out = (float*)d_out;

    const long long OUT_ELEMS  = (long long)B * L * D;          //  4,194,304
    const long long ATTN_ELEMS = (long long)B * H * L * L;      // 67,108,864

    cudaStream_t s0 = 0;                 // the capture/launch stream
    cudaStream_t s2;
    cudaStreamCreateWithFlags(&s2, cudaStreamNonBlocking);
    cudaEvent_t eFork, eJoin;
    cudaEventCreateWithFlags(&eFork, cudaEventDisableTiming);
    cudaEventCreateWithFlags(&eJoin, cudaEventDisableTiming);

    // Stage 0: counts + weight row + accumulator zeroing.
    count_kernel<<<B, L, 0, s0>>>(mask);

    // Fork: big attn_weights fill depends only on count_kernel.
    cudaEventRecord(eFork, s0);
    cudaStreamWaitEvent(s2, eFork, 0);

    if ((long long)out_size >= OUT_ELEMS + ATTN_ELEMS) {
        attn_fill_kernel<<<dim3(256, B), 256, 0, s2>>>(
            (float4*)(out + OUT_ELEMS));
    } else if ((long long)out_size >= ATTN_ELEMS) {
        attn_fill_kernel<<<dim3(256, B), 256, 0, s2>>>((float4*)out);
    }

    // Main-stream chain: colsum -> gemvV -> gemvO -> bcast
    colsum_kernel<<<dim3(D / 256, B, L / ROWS_PER_BLK), 256, 0, s0>>>(value, mask);
    gemv_kernel<<<dim3(D / 8, SPLITS), 256, 0, s0>>>(Wv, bv, 0);
    gemv_kernel<<<dim3(D / 8, SPLITS), 256, 0, s0>>>(Wo, bo, 1);

    if ((long long)out_size >= OUT_ELEMS + ATTN_ELEMS ||
        (long long)out_size < ATTN_ELEMS) {
        bcast_out_kernel<<<dim3(64, B), 256, 0, s0>>>((float4*)out);
    }

    // Join side stream back into the main stream.
    cudaEventRecord(eJoin, s2);
    cudaStreamWaitEvent(s0, eJoin, 0);

    cudaEventDestroy(eFork);
    cudaEventDestroy(eJoin);
    cudaStreamDestroy(s2);
}

// round 6
// speedup vs baseline: 3.4139x; 1.0388x over previous
#include <cuda_runtime.h>

// CounterfactualMultiheadAttention, algebraically reduced.
//
// attn_weights[b,h,q,k] = unmasked[b,k] ? 1/c_b : 0   (c_b = #unmasked keys)
// ctx[b,l,:]            = (mean over unmasked l' of value[b,l',:]) @ Wv.T + bv
// output[b,l,:]         = ctx_row[b] @ Wo.T + bo      (same for every l)
//
// Q, K, Wq, bq, Wk, bk are mathematically dead.
// key_padding_mask is bool in the reference -> int32 in the harness.
//
// Schedule: attn_fill is SELF-SUFFICIENT (derives c_b from the mask in-block)
// and forks at t=0 on a side stream; the count->colsum->gemv->gemv->bcast
// chain hides completely underneath its ~48us of store traffic.

#define B 4
#define L 1024
#define D 1024
#define H 16
#define ROWS_PER_BLK 32   // colsum row-slice size
#define SPLITS 8          // gemv K-splits
#define KS (D / SPLITS)   // 128

// Scratch (no allocations allowed; device globals are the sanctioned path).
__device__ float g_vsum[B][D];     // column sums of value over unmasked rows
__device__ float g_vbar[B][D];     // vmean @ Wv.T + bv
__device__ float g_outrow[B][D];   // vbar  @ Wo.T + bo
__device__ float g_invc[B];        // 1 / c_b

// ---------------------------------------------------------------------------
// Kernel 1: per-batch unmasked count (for gemv) + accumulator zeroing.
__global__ void count_kernel(const int* __restrict__ mask) {
    int b = blockIdx.x;
    int t = threadIdx.x;

    g_vsum[b][t]   = 0.0f;         // replay-safe re-init
    g_vbar[b][t]   = 0.0f;
    g_outrow[b][t] = 0.0f;

    __shared__ int s_cnt;
    if (t == 0) s_cnt = 0;
    __syncthreads();

    int m = mask[b * L + t];
    int local = m ? 0 : 1;
    #pragma unroll
    for (int o = 16; o; o >>= 1) local += __shfl_down_sync(0xFFFFFFFFu, local, o);
    if ((t & 31) == 0) atomicAdd(&s_cnt, local);
    __syncthreads();

    if (t == 0) {
        int c = s_cnt;
        g_invc[b] = 1.0f / (float)(c > 0 ? c : 1);
    }
}

// ---------------------------------------------------------------------------
// Kernel 2: masked column partial sums of value, parallel over row slices.
// grid = (D/256, B, L/ROWS_PER_BLK) = 512 blocks, 256 threads.
__global__ void colsum_kernel(const float* __restrict__ value,
                              const int* __restrict__ mask) {
    int b  = blockIdx.y;
    int j  = blockIdx.x * 256 + threadIdx.x;
    int l0 = blockIdx.z * ROWS_PER_BLK;

    __shared__ int s_mask[ROWS_PER_BLK];
    if (threadIdx.x < ROWS_PER_BLK)
        s_mask[threadIdx.x] = mask[b * L + l0 + threadIdx.x];
    __syncthreads();

    const float* base = value + (size_t)b * L * D + (size_t)l0 * D + j;
    float acc = 0.0f;
    #pragma unroll 8
    for (int l = 0; l < ROWS_PER_BLK; l++) {
        float v = base[(size_t)l * D];
        acc += s_mask[l] ? 0.0f : v;
    }
    atomicAdd(&g_vsum[b][j], acc);
}

// ---------------------------------------------------------------------------
// Kernel 3: split-K GEMV, warp-per-output-row, all 4 batches per warp.
// grid = (D/8, SPLITS), 256 threads. Partial sums atomicAdd into destination.
__global__ void gemv_kernel(const float* __restrict__ W,
                            const float* __restrict__ bias, int mode) {
    int s  = blockIdx.y;
    int k0 = s * KS;

    __shared__ float s_in[B][KS];
    int tid = threadIdx.x;
    for (int i = tid; i < B * KS; i += 256) {
        int b = i / KS, j = i % KS;
        s_in[b][j] = (mode == 0) ? g_vsum[b][k0 + j] * g_invc[b]
                                 : g_vbar[b][k0 + j];
    }
    __syncthreads();

    int warp = tid >> 5, lane = tid & 31;
    int j = blockIdx.x * 8 + warp;
    const float4* wrow = reinterpret_cast<const float4*>(W + (size_t)j * D + k0);
    const float4* x0 = reinterpret_cast<const float4*>(s_in[0]);
    const float4* x1 = reinterpret_cast<const float4*>(s_in[1]);
    const float4* x2 = reinterpret_cast<const float4*>(s_in[2]);
    const float4* x3 = reinterpret_cast<const float4*>(s_in[3]);

    float a0 = 0.f, a1 = 0.f, a2 = 0.f, a3 = 0.f;
    #pragma unroll
    for (int i = lane; i < KS / 4; i += 32) {
        float4 w = wrow[i];
        float4 v;
        v = x0[i]; a0 += w.x*v.x + w.y*v.y + w.z*v.z + w.w*v.w;
        v = x1[i]; a1 += w.x*v.x + w.y*v.y + w.z*v.z + w.w*v.w;
        v = x2[i]; a2 += w.x*v.x + w.y*v.y + w.z*v.z + w.w*v.w;
        v = x3[i]; a3 += w.x*v.x + w.y*v.y + w.z*v.z + w.w*v.w;
    }
    #pragma unroll
    for (int o = 16; o; o >>= 1) {
        a0 += __shfl_down_sync(0xFFFFFFFFu, a0, o);
        a1 += __shfl_down_sync(0xFFFFFFFFu, a1, o);
        a2 += __shfl_down_sync(0xFFFFFFFFu, a2, o);
        a3 += __shfl_down_sync(0xFFFFFFFFu, a3, o);
    }
    if (lane == 0) {
        float bb = (s == 0) ? bias[j] : 0.0f;
        float* dst0 = (mode == 0) ? &g_vbar[0][j] : &g_outrow[0][j];
        float* dst1 = (mode == 0) ? &g_vbar[1][j] : &g_outrow[1][j];
        float* dst2 = (mode == 0) ? &g_vbar[2][j] : &g_outrow[2][j];
        float* dst3 = (mode == 0) ? &g_vbar[3][j] : &g_outrow[3][j];
        atomicAdd(dst0, a0 + bb);
        atomicAdd(dst1, a1 + bb);
        atomicAdd(dst2, a2 + bb);
        atomicAdd(dst3, a3 + bb);
    }
}

// ---------------------------------------------------------------------------
// Kernel 4: broadcast output rows, persistent. grid = (64, B), 256 threads.
__global__ void bcast_out_kernel(float4* __restrict__ out) {
    int b = blockIdx.y;
    int g = blockIdx.x * 256 + threadIdx.x;      // 0..16383
    int j4 = g & (D / 4 - 1);
    float4 v = reinterpret_cast<const float4*>(g_outrow[b])[j4];
    float4* dst = out + (size_t)b * (L * D / 4) + g;
    #pragma unroll
    for (int it = 0; it < 16; it++)
        __stcs(dst + it * 16384, v);
}

// ---------------------------------------------------------------------------
// Kernel 5: fill attn_weights[b,h,q,k], SELF-SUFFICIENT (no dependencies).
// grid = (256, B), 256 threads. Each block covers all 256 int4 mask words of
// its batch (k4 == tid), derives c_b by block reduction, composes its float4
// in registers, then emits 64 independent evict-streaming STG.128s.
__global__ void attn_fill_kernel(float4* __restrict__ aw,
                                 const int* __restrict__ mask) {
    int b   = blockIdx.y;
    int tid = threadIdx.x;
    int g   = blockIdx.x * 256 + tid;            // 0..65535
    int k4  = tid;                               // == g & 255 by construction

    int4 m = reinterpret_cast<const int4*>(mask + b * L)[k4];
    int local = (m.x == 0) + (m.y == 0) + (m.z == 0) + (m.w == 0);

    __shared__ int   s_warp[8];
    __shared__ float s_inv;
    #pragma unroll
    for (int o = 16; o; o >>= 1) local += __shfl_down_sync(0xFFFFFFFFu, local, o);
    if ((tid & 31) == 0) s_warp[tid >> 5] = local;
    __syncthreads();
    if (tid == 0) {
        int c = s_warp[0] + s_warp[1] + s_warp[2] + s_warp[3]
              + s_warp[4] + s_warp[5] + s_warp[6] + s_warp[7];
        s_inv = 1.0f / (float)(c > 0 ? c : 1);
    }
    __syncthreads();
    float inv = s_inv;

    float4 v;
    v.x = m.x ? 0.0f : inv;
    v.y = m.y ? 0.0f : inv;
    v.z = m.z ? 0.0f : inv;
    v.w = m.w ? 0.0f : inv;

    float4* dst = aw + (size_t)b * (H * L * L / 4) + g;
    #pragma unroll
    for (int it = 0; it < 64; it++)
        __stcs(dst + it * 65536, v);
}

// ---------------------------------------------------------------------------
extern "C" void kernel_launch(void* const* d_in, const int* in_sizes, int n_in,
                              void* d_out, int out_size) {
    // Input order: query, key, value, key_padding_mask, Wq, bq, Wk, bk, Wv, bv, Wo, bo
    const float* value = (const float*)d_in[2];
    const int*   mask  = (const int*)d_in[3];
    const float* Wv    = (const float*)d_in[8];
    const float* bv    = (const float*)d_in[9];
    const float* Wo    = (const float*)d_in[10];
    const float* bo    = (const float*)d_in[11];
    float* out = (float*)d_out;

    const long long OUT_ELEMS  = (long long)B * L * D;          //  4,194,304
    const long long ATTN_ELEMS = (long long)B * H * L * L;      // 67,108,864

    cudaStream_t s0 = 0;                 // the capture/launch stream
    cudaStream_t s2;
    cudaStreamCreateWithFlags(&s2, cudaStreamNonBlocking);
    cudaEvent_t eFork, eJoin;
    cudaEventCreateWithFlags(&eFork, cudaEventDisableTiming);
    cudaEventCreateWithFlags(&eJoin, cudaEventDisableTiming);

    // Fork IMMEDIATELY: the fill has no dependencies at all.
    cudaEventRecord(eFork, s0);
    cudaStreamWaitEvent(s2, eFork, 0);

    if ((long long)out_size >= OUT_ELEMS + ATTN_ELEMS) {
        attn_fill_kernel<<<dim3(256, B), 256, 0, s2>>>(
            (float4*)(out + OUT_ELEMS), mask);
    } else if ((long long)out_size >= ATTN_ELEMS) {
        attn_fill_kernel<<<dim3(256, B), 256, 0, s2>>>((float4*)out, mask);
    }

    // Main-stream chain: count -> colsum -> gemvV -> gemvO -> bcast
    count_kernel<<<B, L, 0, s0>>>(mask);
    colsum_kernel<<<dim3(D / 256, B, L / ROWS_PER_BLK), 256, 0, s0>>>(value, mask);
    gemv_kernel<<<dim3(D / 8, SPLITS), 256, 0, s0>>>(Wv, bv, 0);
    gemv_kernel<<<dim3(D / 8, SPLITS), 256, 0, s0>>>(Wo, bo, 1);

    if ((long long)out_size >= OUT_ELEMS + ATTN_ELEMS ||
        (long long)out_size < ATTN_ELEMS) {
        bcast_out_kernel<<<dim3(64, B), 256, 0, s0>>>((float4*)out);
    }

    // Join side stream back into the main stream.
    cudaEventRecord(eJoin, s2);
    cudaStreamWaitEvent(s0, eJoin, 0);

    cudaEventDestroy(eFork);
    cudaEventDestroy(eJoin);
    cudaStreamDestroy(s2);
}

// round 7
// speedup vs baseline: 3.5317x; 1.0345x over previous
#include <cuda_runtime.h>

// CounterfactualMultiheadAttention, algebraically reduced.
//
// attn_weights[b,h,q,k] = unmasked[b,k] ? 1/c_b : 0   (c_b = #unmasked keys)
// ctx[b,l,:]            = (mean over unmasked l' of value[b,l',:]) @ Wv.T + bv
// output[b,l,:]         = ctx_row[b] @ Wo.T + bo      (same for every l)
//
// Q, K, Wq, bq, Wk, bk are mathematically dead.
// key_padding_mask is bool in the reference -> int32 in the harness.
//
// Schedule: self-sufficient attn_fill forks at t=0; the
// count->colsum->gemv->gemv->bcast chain hides under its ~48us of stores.
// Fill blocks own CONTIGUOUS 256KB regions for DRAM page locality.

#define B 4
#define L 1024
#define D 1024
#define H 16
#define ROWS_PER_BLK 32   // colsum row-slice size
#define SPLITS 8          // gemv K-splits
#define KS (D / SPLITS)   // 128

// Scratch (no allocations allowed; device globals are the sanctioned path).
__device__ float g_vsum[B][D];     // column sums of value over unmasked rows
__device__ float g_vbar[B][D];     // vmean @ Wv.T + bv
__device__ float g_outrow[B][D];   // vbar  @ Wo.T + bo
__device__ float g_invc[B];        // 1 / c_b

// ---------------------------------------------------------------------------
// Kernel 1: per-batch unmasked count (for gemv) + accumulator zeroing.
__global__ void count_kernel(const int* __restrict__ mask) {
    int b = blockIdx.x;
    int t = threadIdx.x;

    g_vsum[b][t]   = 0.0f;         // replay-safe re-init
    g_vbar[b][t]   = 0.0f;
    g_outrow[b][t] = 0.0f;

    __shared__ int s_cnt;
    if (t == 0) s_cnt = 0;
    __syncthreads();

    int m = mask[b * L + t];
    int local = m ? 0 : 1;
    #pragma unroll
    for (int o = 16; o; o >>= 1) local += __shfl_down_sync(0xFFFFFFFFu, local, o);
    if ((t & 31) == 0) atomicAdd(&s_cnt, local);
    __syncthreads();

    if (t == 0) {
        int c = s_cnt;
        g_invc[b] = 1.0f / (float)(c > 0 ? c : 1);
    }
}

// ---------------------------------------------------------------------------
// Kernel 2: masked column partial sums of value, parallel over row slices.
// grid = (D/256, B, L/ROWS_PER_BLK) = 512 blocks, 256 threads.
__global__ void colsum_kernel(const float* __restrict__ value,
                              const int* __restrict__ mask) {
    int b  = blockIdx.y;
    int j  = blockIdx.x * 256 + threadIdx.x;
    int l0 = blockIdx.z * ROWS_PER_BLK;

    __shared__ int s_mask[ROWS_PER_BLK];
    if (threadIdx.x < ROWS_PER_BLK)
        s_mask[threadIdx.x] = mask[b * L + l0 + threadIdx.x];
    __syncthreads();

    const float* base = value + (size_t)b * L * D + (size_t)l0 * D + j;
    float acc = 0.0f;
    #pragma unroll 8
    for (int l = 0; l < ROWS_PER_BLK; l++) {
        float v = base[(size_t)l * D];
        acc += s_mask[l] ? 0.0f : v;
    }
    atomicAdd(&g_vsum[b][j], acc);
}

// ---------------------------------------------------------------------------
// Kernel 3: split-K GEMV, warp-per-output-row, all 4 batches per warp.
// grid = (D/8, SPLITS), 256 threads. Partial sums atomicAdd into destination.
__global__ void gemv_kernel(const float* __restrict__ W,
                            const float* __restrict__ bias, int mode) {
    int s  = blockIdx.y;
    int k0 = s * KS;

    __shared__ float s_in[B][KS];
    int tid = threadIdx.x;
    for (int i = tid; i < B * KS; i += 256) {
        int b = i / KS, j = i % KS;
        s_in[b][j] = (mode == 0) ? g_vsum[b][k0 + j] * g_invc[b]
                                 : g_vbar[b][k0 + j];
    }
    __syncthreads();

    int warp = tid >> 5, lane = tid & 31;
    int j = blockIdx.x * 8 + warp;
    const float4* wrow = reinterpret_cast<const float4*>(W + (size_t)j * D + k0);
    const float4* x0 = reinterpret_cast<const float4*>(s_in[0]);
    const float4* x1 = reinterpret_cast<const float4*>(s_in[1]);
    const float4* x2 = reinterpret_cast<const float4*>(s_in[2]);
    const float4* x3 = reinterpret_cast<const float4*>(s_in[3]);

    float a0 = 0.f, a1 = 0.f, a2 = 0.f, a3 = 0.f;
    #pragma unroll
    for (int i = lane; i < KS / 4; i += 32) {
        float4 w = wrow[i];
        float4 v;
        v = x0[i]; a0 += w.x*v.x + w.y*v.y + w.z*v.z + w.w*v.w;
        v = x1[i]; a1 += w.x*v.x + w.y*v.y + w.z*v.z + w.w*v.w;
        v = x2[i]; a2 += w.x*v.x + w.y*v.y + w.z*v.z + w.w*v.w;
        v = x3[i]; a3 += w.x*v.x + w.y*v.y + w.z*v.z + w.w*v.w;
    }
    #pragma unroll
    for (int o = 16; o; o >>= 1) {
        a0 += __shfl_down_sync(0xFFFFFFFFu, a0, o);
        a1 += __shfl_down_sync(0xFFFFFFFFu, a1, o);
        a2 += __shfl_down_sync(0xFFFFFFFFu, a2, o);
        a3 += __shfl_down_sync(0xFFFFFFFFu, a3, o);
    }
    if (lane == 0) {
        float bb = (s == 0) ? bias[j] : 0.0f;
        float* dst0 = (mode == 0) ? &g_vbar[0][j] : &g_outrow[0][j];
        float* dst1 = (mode == 0) ? &g_vbar[1][j] : &g_outrow[1][j];
        float* dst2 = (mode == 0) ? &g_vbar[2][j] : &g_outrow[2][j];
        float* dst3 = (mode == 0) ? &g_vbar[3][j] : &g_outrow[3][j];
        atomicAdd(dst0, a0 + bb);
        atomicAdd(dst1, a1 + bb);
        atomicAdd(dst2, a2 + bb);
        atomicAdd(dst3, a3 + bb);
    }
}

// ---------------------------------------------------------------------------
// Kernel 4: broadcast output rows, contiguous regions. grid = (64, B).
// Per block: 4096 consecutive float4 (64KB... actually 16KB x4). base is a
// multiple of 256 => the source index is just tid, loop-invariant.
__global__ void bcast_out_kernel(float4* __restrict__ out) {
    int b   = blockIdx.y;
    int tid = threadIdx.x;
    float4 v = reinterpret_cast<const float4*>(g_outrow[b])[tid];
    float4* dst = out + (size_t)b * (L * D / 4) + (size_t)blockIdx.x * 4096;
    #pragma unroll
    for (int it = 0; it < 16; it++)
        __stcs(dst + it * 256 + tid, v);
}

// ---------------------------------------------------------------------------
// Kernel 5: fill attn_weights[b,h,q,k], SELF-SUFFICIENT, contiguous regions.
// grid = (256, B), 256 threads. Each block derives c_b from the batch's mask
// row (one int4 per thread), composes its float4 in a register, then walks a
// CONTIGUOUS 16384-float4 (256KB) region: iteration it writes
// base + it*256 + tid. base/stride are multiples of 256 => k4 == tid always.
__global__ void attn_fill_kernel(float4* __restrict__ aw,
                                 const int* __restrict__ mask) {
    int b   = blockIdx.y;
    int tid = threadIdx.x;

    int4 m = reinterpret_cast<const int4*>(mask + b * L)[tid];
    int local = (m.x == 0) + (m.y == 0) + (m.z == 0) + (m.w == 0);

    __shared__ int   s_warp[8];
    __shared__ float s_inv;
    #pragma unroll
    for (int o = 16; o; o >>= 1) local += __shfl_down_sync(0xFFFFFFFFu, local, o);
    if ((tid & 31) == 0) s_warp[tid >> 5] = local;
    __syncthreads();
    if (tid == 0) {
        int c = s_warp[0] + s_warp[1] + s_warp[2] + s_warp[3]
              + s_warp[4] + s_warp[5] + s_warp[6] + s_warp[7];
        s_inv = 1.0f / (float)(c > 0 ? c : 1);
    }
    __syncthreads();
    float inv = s_inv;

    float4 v;
    v.x = m.x ? 0.0f : inv;
    v.y = m.y ? 0.0f : inv;
    v.z = m.z ? 0.0f : inv;
    v.w = m.w ? 0.0f : inv;

    float4* dst = aw + (size_t)b * (H * L * L / 4)
                     + (size_t)blockIdx.x * 16384;
    #pragma unroll
    for (int it = 0; it < 64; it++)
        __stcs(dst + it * 256 + tid, v);
}

// ---------------------------------------------------------------------------
extern "C" void kernel_launch(void* const* d_in, const int* in_sizes, int n_in,
                              void* d_out, int out_size) {
    // Input order: query, key, value, key_padding_mask, Wq, bq, Wk, bk, Wv, bv, Wo, bo
    const float* value = (const float*)d_in[2];
    const int*   mask  = (const int*)d_in[3];
    const float* Wv    = (const float*)d_in[8];
    const float* bv    = (const float*)d_in[9];
    const float* Wo    = (const float*)d_in[10];
    const float* bo    = (const float*)d_in[11];
    float* out = (float*)d_out;

    const long long OUT_ELEMS  = (long long)B * L * D;          //  4,194,304
    const long long ATTN_ELEMS = (long long)B * H * L * L;      // 67,108,864

    cudaStream_t s0 = 0;                 // the capture/launch stream
    cudaStream_t s2;
    cudaStreamCreateWithFlags(&s2, cudaStreamNonBlocking);
    cudaEvent_t eFork, eJoin;
    cudaEventCreateWithFlags(&eFork, cudaEventDisableTiming);
    cudaEventCreateWithFlags(&eJoin, cudaEventDisableTiming);

    // Fork IMMEDIATELY: the fill has no dependencies at all.
    cudaEventRecord(eFork, s0);
    cudaStreamWaitEvent(s2, eFork, 0);

    if ((long long)out_size >= OUT_ELEMS + ATTN_ELEMS) {
        attn_fill_kernel<<<dim3(256, B), 256, 0, s2>>>(
            (float4*)(out + OUT_ELEMS), mask);
    } else if ((long long)out_size >= ATTN_ELEMS) {
        attn_fill_kernel<<<dim3(256, B), 256, 0, s2>>>((float4*)out, mask);
    }

    // Main-stream chain: count -> colsum -> gemvV -> gemvO -> bcast
    count_kernel<<<B, L, 0, s0>>>(mask);
    colsum_kernel<<<dim3(D / 256, B, L / ROWS_PER_BLK), 256, 0, s0>>>(value, mask);
    gemv_kernel<<<dim3(D / 8, SPLITS), 256, 0, s0>>>(Wv, bv, 0);
    gemv_kernel<<<dim3(D / 8, SPLITS), 256, 0, s0>>>(Wo, bo, 1);

    if ((long long)out_size >= OUT_ELEMS + ATTN_ELEMS ||
        (long long)out_size < ATTN_ELEMS) {
        bcast_out_kernel<<<dim3(64, B), 256, 0, s0>>>((float4*)out);
    }

    // Join side stream back into the main stream.
    cudaEventRecord(eJoin, s2);
    cudaStreamWaitEvent(s0, eJoin, 0);

    cudaEventDestroy(eFork);
    cudaEventDestroy(eJoin);
    cudaStreamDestroy(s2);
}